// round 15
// baseline (speedup 1.0000x reference)
#include <cuda_runtime.h>
#include <cuda_fp16.h>
#include <cstdint>

#define T_DIM  4096
#define C_DIM  2048
#define K_DIM  2048
#define S_CHUNKS 32
#define L_CHUNK  128

#define KTILE  64
#define NKT    (K_DIM / KTILE)        // 32
#define ROWB   144                    // padded row bytes (72 fp16)
#define SECT   (128 * ROWB)           // 18432
#define STAGE_BYTES (2 * SECT)        // 36864
#define NSTAGE 3
#define SMEM_TOTAL (NSTAGE * STAGE_BYTES)   // 110592 (108KB) -> 2 CTAs/SM

typedef __half f16;

// ===================== PTX helpers =====================
__device__ __forceinline__ uint32_t smem_u32(const void* p) {
    uint32_t a;
    asm("{ .reg .u64 t; cvta.to.shared.u64 t, %1; cvt.u32.u64 %0, t; }" : "=r"(a) : "l"(p));
    return a;
}
__device__ __forceinline__ void cp16(uint32_t smem, const void* g) {
    asm volatile("cp.async.cg.shared.global [%0], [%1], 16;" :: "r"(smem), "l"(g));
}
#define CP_COMMIT() asm volatile("cp.async.commit_group;" ::: "memory")
#define CP_WAIT(n)  asm volatile("cp.async.wait_group %0;" :: "n"(n) : "memory")

__device__ __forceinline__ void ldsm4(uint32_t& r0, uint32_t& r1, uint32_t& r2, uint32_t& r3,
                                      uint32_t addr) {
    asm volatile("ldmatrix.sync.aligned.m8n8.x4.shared.b16 {%0,%1,%2,%3}, [%4];"
                 : "=r"(r0), "=r"(r1), "=r"(r2), "=r"(r3) : "r"(addr));
}
__device__ __forceinline__ void mma16816(float& c0, float& c1, float& c2, float& c3,
                                         uint32_t a0, uint32_t a1, uint32_t a2, uint32_t a3,
                                         uint32_t b0, uint32_t b1) {
    asm volatile("mma.sync.aligned.m16n8k16.row.col.f32.f16.f16.f32 "
                 "{%0,%1,%2,%3}, {%4,%5,%6,%7}, {%8,%9}, {%0,%1,%2,%3};"
                 : "+f"(c0), "+f"(c1), "+f"(c2), "+f"(c3)
                 : "r"(a0), "r"(a1), "r"(a2), "r"(a3), "r"(b0), "r"(b1));
}

// ===================== scratch =====================
__device__ f16   g_kh[T_DIM * C_DIM];
__device__ f16   g_vh[T_DIM * C_DIM];
__device__ f16   g_rh[T_DIM * C_DIM];
__device__ float g_carryA[S_CHUNKS * C_DIM];
__device__ float g_carryB[S_CHUNKS * C_DIM];

__device__ f16 g_ax[3][T_DIM * K_DIM];
__device__ f16 g_wt[4][C_DIM * K_DIM];
__device__ f16 g_g[T_DIM * C_DIM];

// ===================== pre-pass: mix to fp16 =====================
__global__ void mix_split(const float* __restrict__ x, const float* __restrict__ mk,
                          const float* __restrict__ mv, const float* __restrict__ mr)
{
    int idx = blockIdx.x * 256 + threadIdx.x;
    int m  = idx >> 9;
    int c4 = (idx & 511) << 2;
    size_t off = (size_t)m * C_DIM + c4;
    float4 xc = *(const float4*)(x + off);
    float4 xp = make_float4(0.f, 0.f, 0.f, 0.f);
    if (m > 0) xp = *(const float4*)(x + off - C_DIM);
    const float* mixes[3] = { mk, mv, mr };
#pragma unroll
    for (int p = 0; p < 3; p++) {
        float4 mx = *(const float4*)(mixes[p] + c4);
        f16 h[4];
        h[0] = __float2half_rn(xc.x * mx.x + xp.x * (1.f - mx.x));
        h[1] = __float2half_rn(xc.y * mx.y + xp.y * (1.f - mx.y));
        h[2] = __float2half_rn(xc.z * mx.z + xp.z * (1.f - mx.z));
        h[3] = __float2half_rn(xc.w * mx.w + xp.w * (1.f - mx.w));
        *(uint2*)(&g_ax[p][off]) = *(uint2*)h;
    }
}

// ===================== pre-pass: weight transpose to fp16 [N,K] =====================
__global__ void wsplit_pair(const float* __restrict__ W0, const float* __restrict__ W1,
                            int base)
{
    __shared__ float t[32][33];
    const float* W = (blockIdx.z == 0) ? W0 : W1;
    int which = base + blockIdx.z;
    int n0 = blockIdx.x * 32, k0 = blockIdx.y * 32;
    int tx = threadIdx.x, ty = threadIdx.y;
#pragma unroll
    for (int i = 0; i < 32; i += 8)
        t[ty + i][tx] = W[(size_t)(k0 + ty + i) * C_DIM + n0 + tx];
    __syncthreads();
#pragma unroll
    for (int i = 0; i < 32; i += 8)
        g_wt[which][(size_t)(n0 + ty + i) * K_DIM + k0 + tx] =
            __float2half_rn(t[tx][ty + i]);
}

// ===================== HMMA GEMM (fp16, CTA 128x128, persistent) =====
__device__ __forceinline__ void load_stage(
    uint32_t sb, int slot, int kt, int m0, int n0, int tid,
    const f16* __restrict__ A, const f16* __restrict__ B)
{
    const int k0 = kt * KTILE;
    uint32_t base = sb + slot * STAGE_BYTES;
#pragma unroll
    for (int t = 0; t < 4; t++) {
        int id = tid + t * 512;
        int ch = (id & 7) << 3;
        int row = (id & 1023) >> 3;
        uint32_t so = base + (id >> 10) * SECT + row * ROWB + ch * 2;
        const f16* src = (id < 1024) ? A : B;
        int grow = ((id < 1024) ? m0 : n0) + row;
        cp16(so, src + (size_t)grow * K_DIM + k0 + ch);
    }
    CP_COMMIT();
}

struct Frag {
    uint32_t a[2][4];
    uint32_t b[8];
};

__device__ __forceinline__ void ld_frags(Frag& f, uint32_t abase, uint32_t bbase, int kk)
{
    uint32_t ao = abase + kk * 32;
    uint32_t bo = bbase + kk * 32;
#pragma unroll
    for (int mi = 0; mi < 2; mi++)
        ldsm4(f.a[mi][0], f.a[mi][1], f.a[mi][2], f.a[mi][3], ao + mi * 16 * ROWB);
#pragma unroll
    for (int q = 0; q < 2; q++)
        ldsm4(f.b[q * 4], f.b[q * 4 + 1], f.b[q * 4 + 2], f.b[q * 4 + 3],
              bo + q * 16 * ROWB);
}

__device__ __forceinline__ void compute_frag(const Frag& f, float acc[2][4][4])
{
#pragma unroll
    for (int mi = 0; mi < 2; mi++) {
#pragma unroll
        for (int nt = 0; nt < 4; nt++) {
            int i0 = (nt >> 1) * 4 + (nt & 1);
            float* c = acc[mi][nt];
            mma16816(c[0], c[1], c[2], c[3],
                     f.a[mi][0], f.a[mi][1], f.a[mi][2], f.a[mi][3],
                     f.b[i0], f.b[i0 + 2]);
        }
    }
}

// one 128x128 tile; assumes caller did prologue for stages 0,1 of this tile
__device__ __forceinline__ void gemm_tile(
    uint32_t sb, int tid, int wid, int lane,
    const f16* __restrict__ A, const f16* __restrict__ B,
    float* __restrict__ Cf, f16* __restrict__ Ch, int half_out,
    int m0, int n0)
{
    const int warp_m = wid >> 2;
    const int warp_n = wid & 3;

    float acc[2][4][4];
#pragma unroll
    for (int i = 0; i < 2; i++)
#pragma unroll
        for (int j = 0; j < 4; j++)
#pragma unroll
            for (int q = 0; q < 4; q++) acc[i][j][q] = 0.f;

    const uint32_t lrow = lane & 15;
    const uint32_t lcol = (lane >> 4) << 3;
    const uint32_t aoff = (warp_m * 32 + lrow) * ROWB + lcol * 2;
    const uint32_t boff = SECT + (warp_n * 32 + lrow) * ROWB + lcol * 2;

    Frag fr[2];

    for (int kt = 0; kt < NKT; kt++) {
        const int s = kt % NSTAGE;
        CP_WAIT(1);
        __syncthreads();

        uint32_t stage = sb + s * STAGE_BYTES;
        uint32_t abase = stage + aoff;
        uint32_t bbase = stage + boff;

        ld_frags(fr[0], abase, bbase, 0);

        if (kt + 2 < NKT)
            load_stage(sb, (kt + 2) % NSTAGE, kt + 2, m0, n0, tid, A, B);
        else
            CP_COMMIT();

#pragma unroll
        for (int kk = 0; kk < 4; kk++) {
            if (kk < 3)
                ld_frags(fr[(kk + 1) & 1], abase, bbase, kk + 1);
            compute_frag(fr[kk & 1], acc);
        }
    }
    // all smem reads of this tile complete before next tile's prologue writes
    __syncthreads();

    const int er = lane >> 2;
    const int ec = (lane & 3) * 2;
    if (!half_out) {
#pragma unroll
        for (int mi = 0; mi < 2; mi++)
#pragma unroll
            for (int nt = 0; nt < 4; nt++) {
                int r = m0 + warp_m * 32 + mi * 16 + er;
                int c = n0 + warp_n * 32 + nt * 8 + ec;
                float* c0 = Cf + (size_t)r * 2048 + c;
                *(float2*)c0              = make_float2(acc[mi][nt][0], acc[mi][nt][1]);
                *(float2*)(c0 + 8 * 2048) = make_float2(acc[mi][nt][2], acc[mi][nt][3]);
            }
    } else {
#pragma unroll
        for (int mi = 0; mi < 2; mi++)
#pragma unroll
            for (int nt = 0; nt < 4; nt++) {
                int r = m0 + warp_m * 32 + mi * 16 + er;
                int c = n0 + warp_n * 32 + nt * 8 + ec;
                f16* c0 = Ch + (size_t)r * 2048 + c;
                __half2 h0, h1;
                h0.x = __float2half_rn(acc[mi][nt][0]);
                h0.y = __float2half_rn(acc[mi][nt][1]);
                h1.x = __float2half_rn(acc[mi][nt][2]);
                h1.y = __float2half_rn(acc[mi][nt][3]);
                *(__half2*)c0              = h0;
                *(__half2*)(c0 + 8 * 2048) = h1;
            }
    }
}

// persistent fused k/v/r: 1536 tiles = 3 mats x 32 m x 16 n
__global__ void __launch_bounds__(512, 2) gemm_qkv(int ntiles)
{
    extern __shared__ __align__(128) char smem[];
    uint32_t sb = smem_u32(smem);
    const int tid = threadIdx.x, wid = tid >> 5, lane = tid & 31;

    for (int tile = blockIdx.x; tile < ntiles; tile += gridDim.x) {
        int p   = tile >> 9;              // 0..2
        int rem = tile & 511;
        int m0  = (rem >> 4) << 7;
        int n0  = (rem & 15) << 7;
        const f16* A = g_ax[p];
        const f16* B = g_wt[p];
        f16* C = (p == 0) ? g_kh : (p == 1) ? g_vh : g_rh;

        load_stage(sb, 0, 0, m0, n0, tid, A, B);
        load_stage(sb, 1, 1, m0, n0, tid, A, B);
        gemm_tile(sb, tid, wid, lane, A, B, nullptr, C, 1, m0, n0);
    }
}

// persistent output projection: 512 tiles = 32 m x 16 n
__global__ void __launch_bounds__(512, 2) gemm_out(float* __restrict__ out, int ntiles)
{
    extern __shared__ __align__(128) char smem[];
    uint32_t sb = smem_u32(smem);
    const int tid = threadIdx.x, wid = tid >> 5, lane = tid & 31;

    for (int tile = blockIdx.x; tile < ntiles; tile += gridDim.x) {
        int m0 = (tile >> 4) << 7;
        int n0 = (tile & 15) << 7;
        load_stage(sb, 0, 0, m0, n0, tid, g_g, g_wt[3]);
        load_stage(sb, 1, 1, m0, n0, tid, g_g, g_wt[3]);
        gemm_tile(sb, tid, wid, lane, g_g, g_wt[3], out, nullptr, 0, m0, n0);
    }
}

// ===================== WKV chunked scan (2-pass; prefix folded into pass3) ===
__global__ void wkv_pass1(const float* __restrict__ tdecay)
{
    int s = blockIdx.x >> 3;
    int c = ((blockIdx.x & 7) << 8) + threadIdx.x;
    float q = __expf(-__expf(tdecay[c]));
    float d = __expf(-q);
    float A = 0.f, B = 0.f;
    int base = s * L_CHUNK;
    for (int j = 0; j < L_CHUNK; j++) {
        size_t off = (size_t)(base + j) * C_DIM + c;
        float e = __expf(__half2float(g_kh[off]));
        float vv = __half2float(g_vh[off]);
        A = d * A + e * vv;
        B = d * B + e;
    }
    g_carryA[s * C_DIM + c] = A;
    g_carryB[s * C_DIM + c] = B;
}

__global__ void wkv_pass3(const float* __restrict__ tdecay,
                          const float* __restrict__ tfirst)
{
    int s = blockIdx.x >> 3;
    int c = ((blockIdx.x & 7) << 8) + threadIdx.x;
    float q = __expf(-__expf(tdecay[c]));
    float d = __expf(-q);
    float dL = __expf(-q * (float)L_CHUNK);
    float eu = __expf(tfirst[c]);

    float A = 0.f, B = 0.f;
    for (int t = 0; t < s; t++) {
        A = dL * A + g_carryA[t * C_DIM + c];
        B = dL * B + g_carryB[t * C_DIM + c];
    }

    int base = s * L_CHUNK;
    for (int j = 0; j < L_CHUNK; j++) {
        size_t off = (size_t)(base + j) * C_DIM + c;
        float kk = __half2float(g_kh[off]);
        float vv = __half2float(g_vh[off]);
        float rr = __half2float(g_rh[off]);
        float e = __expf(kk);
        float eue = eu * e;
        float wkv = (A + eue * vv) / (B + eue);
        float sr = 1.f / (1.f + __expf(-rr));
        g_g[off] = __float2half_rn(sr * wkv);
        A = d * A + e * vv;
        B = d * B + e;
    }
}

// ===================== launch =====================
extern "C" void kernel_launch(void* const* d_in, const int* in_sizes, int n_in,
                              void* d_out, int out_size)
{
    const float* x  = (const float*)d_in[0];
    const float* tf = (const float*)d_in[1];
    const float* td = (const float*)d_in[2];
    const float* mk = (const float*)d_in[3];
    const float* mv = (const float*)d_in[4];
    const float* mr = (const float*)d_in[5];
    const float* Wk = (const float*)d_in[6];
    const float* Wv = (const float*)d_in[7];
    const float* Wr = (const float*)d_in[8];
    const float* Wo = (const float*)d_in[9];
    float* out = (float*)d_out;

    static int nsm = 0;
    if (!nsm) {
        cudaDeviceGetAttribute(&nsm, cudaDevAttrMultiProcessorCount, 0);
        cudaFuncSetAttribute(gemm_qkv, cudaFuncAttributeMaxDynamicSharedMemorySize, SMEM_TOTAL);
        cudaFuncSetAttribute(gemm_out, cudaFuncAttributeMaxDynamicSharedMemorySize, SMEM_TOTAL);
    }
    const int NQKV = 1536, NOUT = 512;
    int gq = 2 * nsm; if (gq > NQKV) gq = NQKV;
    int go = 2 * nsm; if (go > NOUT) go = NOUT;

    // 1: mix to fp16
    mix_split<<<(T_DIM * C_DIM / 4) / 256, 256>>>(x, mk, mv, mr);
    // 2,3: weight transpose
    dim3 wgrid(C_DIM / 32, K_DIM / 32, 2), wblk(32, 8);
    wsplit_pair<<<wgrid, wblk>>>(Wk, Wv, 0);
    wsplit_pair<<<wgrid, wblk>>>(Wr, Wo, 2);

    // 4: persistent fused k/v/r projections
    gemm_qkv<<<gq, 512, SMEM_TOTAL>>>(NQKV);

    // 5,6: WKV scan + gate
    wkv_pass1<<<S_CHUNKS * (C_DIM / 256), 256>>>(td);
    wkv_pass3<<<S_CHUNKS * (C_DIM / 256), 256>>>(td, tf);

    // 7: persistent output projection
    gemm_out<<<go, 512, SMEM_TOTAL>>>(out, NOUT);
}

// round 17
// speedup vs baseline: 1.0628x; 1.0628x over previous
#include <cuda_runtime.h>
#include <cuda_fp16.h>
#include <cstdint>

#define T_DIM  4096
#define C_DIM  2048
#define K_DIM  2048
#define S_CHUNKS 32
#define L_CHUNK  128

#define KTILE  64
#define NKT    (K_DIM / KTILE)        // 32
#define ROWB   144                    // padded row bytes (72 fp16)
#define SECT   (128 * ROWB)           // 18432
#define STAGE_BYTES (2 * SECT)        // 36864
#define NSTAGE 3
#define SMEM_TOTAL (NSTAGE * STAGE_BYTES)   // 110592 (108KB) -> 2 CTAs/SM

typedef __half f16;

// ===================== PTX helpers =====================
__device__ __forceinline__ uint32_t smem_u32(const void* p) {
    uint32_t a;
    asm("{ .reg .u64 t; cvta.to.shared.u64 t, %1; cvt.u32.u64 %0, t; }" : "=r"(a) : "l"(p));
    return a;
}
__device__ __forceinline__ void cp16(uint32_t smem, const void* g) {
    asm volatile("cp.async.cg.shared.global [%0], [%1], 16;" :: "r"(smem), "l"(g));
}
#define CP_COMMIT() asm volatile("cp.async.commit_group;" ::: "memory")
#define CP_WAIT(n)  asm volatile("cp.async.wait_group %0;" :: "n"(n) : "memory")

__device__ __forceinline__ void ldsm4(uint32_t& r0, uint32_t& r1, uint32_t& r2, uint32_t& r3,
                                      uint32_t addr) {
    asm volatile("ldmatrix.sync.aligned.m8n8.x4.shared.b16 {%0,%1,%2,%3}, [%4];"
                 : "=r"(r0), "=r"(r1), "=r"(r2), "=r"(r3) : "r"(addr));
}
__device__ __forceinline__ void mma16816(float& c0, float& c1, float& c2, float& c3,
                                         uint32_t a0, uint32_t a1, uint32_t a2, uint32_t a3,
                                         uint32_t b0, uint32_t b1) {
    asm volatile("mma.sync.aligned.m16n8k16.row.col.f32.f16.f16.f32 "
                 "{%0,%1,%2,%3}, {%4,%5,%6,%7}, {%8,%9}, {%0,%1,%2,%3};"
                 : "+f"(c0), "+f"(c1), "+f"(c2), "+f"(c3)
                 : "r"(a0), "r"(a1), "r"(a2), "r"(a3), "r"(b0), "r"(b1));
}

// ===================== scratch =====================
__device__ f16   g_kh[T_DIM * C_DIM];
__device__ f16   g_vh[T_DIM * C_DIM];
__device__ f16   g_rh[T_DIM * C_DIM];
__device__ float g_carryA[S_CHUNKS * C_DIM];
__device__ float g_carryB[S_CHUNKS * C_DIM];

__device__ f16 g_ax[3][T_DIM * K_DIM];
__device__ f16 g_wt[4][C_DIM * K_DIM];
__device__ f16 g_g[T_DIM * C_DIM];

// ===================== pre-pass: mix to fp16 =====================
__global__ void mix_split(const float* __restrict__ x, const float* __restrict__ mk,
                          const float* __restrict__ mv, const float* __restrict__ mr)
{
    int idx = blockIdx.x * 256 + threadIdx.x;
    int m  = idx >> 9;
    int c4 = (idx & 511) << 2;
    size_t off = (size_t)m * C_DIM + c4;
    float4 xc = *(const float4*)(x + off);
    float4 xp = make_float4(0.f, 0.f, 0.f, 0.f);
    if (m > 0) xp = *(const float4*)(x + off - C_DIM);
    const float* mixes[3] = { mk, mv, mr };
#pragma unroll
    for (int p = 0; p < 3; p++) {
        float4 mx = *(const float4*)(mixes[p] + c4);
        f16 h[4];
        h[0] = __float2half_rn(xc.x * mx.x + xp.x * (1.f - mx.x));
        h[1] = __float2half_rn(xc.y * mx.y + xp.y * (1.f - mx.y));
        h[2] = __float2half_rn(xc.z * mx.z + xp.z * (1.f - mx.z));
        h[3] = __float2half_rn(xc.w * mx.w + xp.w * (1.f - mx.w));
        *(uint2*)(&g_ax[p][off]) = *(uint2*)h;
    }
}

// ===================== pre-pass: 4 weight transposes in one launch =====================
__global__ void wsplit_quad(const float* __restrict__ W0, const float* __restrict__ W1,
                            const float* __restrict__ W2, const float* __restrict__ W3)
{
    __shared__ float t[32][33];
    int which = blockIdx.z;
    const float* W = (which == 0) ? W0 : (which == 1) ? W1 : (which == 2) ? W2 : W3;
    int n0 = blockIdx.x * 32, k0 = blockIdx.y * 32;
    int tx = threadIdx.x, ty = threadIdx.y;
#pragma unroll
    for (int i = 0; i < 32; i += 8)
        t[ty + i][tx] = W[(size_t)(k0 + ty + i) * C_DIM + n0 + tx];
    __syncthreads();
#pragma unroll
    for (int i = 0; i < 32; i += 8)
        g_wt[which][(size_t)(n0 + ty + i) * K_DIM + k0 + tx] =
            __float2half_rn(t[tx][ty + i]);
}

// ===================== HMMA GEMM (fp16, CTA 128x128, 2 CTAs/SM) =====
__device__ __forceinline__ void load_stage(
    uint32_t sb, int slot, int kt, int m0, int n0, int tid,
    const f16* __restrict__ A, const f16* __restrict__ B)
{
    const int k0 = kt * KTILE;
    uint32_t base = sb + slot * STAGE_BYTES;
#pragma unroll
    for (int t = 0; t < 4; t++) {
        int id = tid + t * 512;
        int ch = (id & 7) << 3;
        int row = (id & 1023) >> 3;
        uint32_t so = base + (id >> 10) * SECT + row * ROWB + ch * 2;
        const f16* src = (id < 1024) ? A : B;
        int grow = ((id < 1024) ? m0 : n0) + row;
        cp16(so, src + (size_t)grow * K_DIM + k0 + ch);
    }
    CP_COMMIT();
}

struct Frag {
    uint32_t a[2][4];
    uint32_t b[8];
};

__device__ __forceinline__ void ld_frags(Frag& f, uint32_t abase, uint32_t bbase, int kk)
{
    uint32_t ao = abase + kk * 32;
    uint32_t bo = bbase + kk * 32;
#pragma unroll
    for (int mi = 0; mi < 2; mi++)
        ldsm4(f.a[mi][0], f.a[mi][1], f.a[mi][2], f.a[mi][3], ao + mi * 16 * ROWB);
#pragma unroll
    for (int q = 0; q < 2; q++)
        ldsm4(f.b[q * 4], f.b[q * 4 + 1], f.b[q * 4 + 2], f.b[q * 4 + 3],
              bo + q * 16 * ROWB);
}

__device__ __forceinline__ void compute_frag(const Frag& f, float acc[2][4][4])
{
#pragma unroll
    for (int mi = 0; mi < 2; mi++) {
#pragma unroll
        for (int nt = 0; nt < 4; nt++) {
            int i0 = (nt >> 1) * 4 + (nt & 1);
            float* c = acc[mi][nt];
            mma16816(c[0], c[1], c[2], c[3],
                     f.a[mi][0], f.a[mi][1], f.a[mi][2], f.a[mi][3],
                     f.b[i0], f.b[i0 + 2]);
        }
    }
}

__device__ __forceinline__ void gemm_body(
    const f16* __restrict__ A, const f16* __restrict__ B,
    float* __restrict__ Cf, f16* __restrict__ Ch, int half_out, int moff)
{
    extern __shared__ __align__(128) char smem[];
    uint32_t sb = smem_u32(smem);
    const int tid = threadIdx.x;
    const int wid = tid >> 5, lane = tid & 31;
    const int warp_m = wid >> 2;
    const int warp_n = wid & 3;
    const int m0 = moff + blockIdx.y * 128;
    const int n0 = blockIdx.x * 128;

    float acc[2][4][4];
#pragma unroll
    for (int i = 0; i < 2; i++)
#pragma unroll
        for (int j = 0; j < 4; j++)
#pragma unroll
            for (int q = 0; q < 4; q++) acc[i][j][q] = 0.f;

    load_stage(sb, 0, 0, m0, n0, tid, A, B);
    load_stage(sb, 1, 1, m0, n0, tid, A, B);

    const uint32_t lrow = lane & 15;
    const uint32_t lcol = (lane >> 4) << 3;
    const uint32_t aoff = (warp_m * 32 + lrow) * ROWB + lcol * 2;
    const uint32_t boff = SECT + (warp_n * 32 + lrow) * ROWB + lcol * 2;

    Frag fr[2];

    for (int kt = 0; kt < NKT; kt++) {
        const int s = kt % NSTAGE;
        CP_WAIT(1);
        __syncthreads();

        uint32_t stage = sb + s * STAGE_BYTES;
        uint32_t abase = stage + aoff;
        uint32_t bbase = stage + boff;

        ld_frags(fr[0], abase, bbase, 0);

        if (kt + 2 < NKT)
            load_stage(sb, (kt + 2) % NSTAGE, kt + 2, m0, n0, tid, A, B);
        else
            CP_COMMIT();

#pragma unroll
        for (int kk = 0; kk < 4; kk++) {
            if (kk < 3)
                ld_frags(fr[(kk + 1) & 1], abase, bbase, kk + 1);
            compute_frag(fr[kk & 1], acc);
        }
    }

    const int er = lane >> 2;
    const int ec = (lane & 3) * 2;
    if (!half_out) {
#pragma unroll
        for (int mi = 0; mi < 2; mi++)
#pragma unroll
            for (int nt = 0; nt < 4; nt++) {
                int r = m0 + warp_m * 32 + mi * 16 + er;
                int c = n0 + warp_n * 32 + nt * 8 + ec;
                float* c0 = Cf + (size_t)r * 2048 + c;
                *(float2*)c0              = make_float2(acc[mi][nt][0], acc[mi][nt][1]);
                *(float2*)(c0 + 8 * 2048) = make_float2(acc[mi][nt][2], acc[mi][nt][3]);
            }
    } else {
#pragma unroll
        for (int mi = 0; mi < 2; mi++)
#pragma unroll
            for (int nt = 0; nt < 4; nt++) {
                int r = m0 + warp_m * 32 + mi * 16 + er;
                int c = n0 + warp_n * 32 + nt * 8 + ec;
                f16* c0 = Ch + (size_t)r * 2048 + c;
                __half2 h0, h1;
                h0.x = __float2half_rn(acc[mi][nt][0]);
                h0.y = __float2half_rn(acc[mi][nt][1]);
                h1.x = __float2half_rn(acc[mi][nt][2]);
                h1.y = __float2half_rn(acc[mi][nt][3]);
                *(__half2*)c0              = h0;
                *(__half2*)(c0 + 8 * 2048) = h1;
            }
    }
}

__global__ void __launch_bounds__(512, 2) gemm_qkv()
{
    int p = blockIdx.z;
    f16* C = (p == 0) ? g_kh : (p == 1) ? g_vh : g_rh;
    gemm_body(g_ax[p], g_wt[p], nullptr, C, 1, 0);
}

__global__ void __launch_bounds__(512, 2) gemm_out(float* __restrict__ out, int moff)
{
    gemm_body(g_g, g_wt[3], out, nullptr, 0, moff);
}

// ===================== WKV chunked scan (2-pass; prefix folded into pass3) ===
__global__ void wkv_pass1(const float* __restrict__ tdecay)
{
    int s = blockIdx.x >> 3;
    int c = ((blockIdx.x & 7) << 8) + threadIdx.x;
    float q = __expf(-__expf(tdecay[c]));
    float d = __expf(-q);
    float A = 0.f, B = 0.f;
    int base = s * L_CHUNK;
    for (int j = 0; j < L_CHUNK; j++) {
        size_t off = (size_t)(base + j) * C_DIM + c;
        float e = __expf(__half2float(g_kh[off]));
        float vv = __half2float(g_vh[off]);
        A = d * A + e * vv;
        B = d * B + e;
    }
    g_carryA[s * C_DIM + c] = A;
    g_carryB[s * C_DIM + c] = B;
}

__global__ void wkv_pass3(const float* __restrict__ tdecay,
                          const float* __restrict__ tfirst, int soff)
{
    int s = (blockIdx.x >> 3) + soff;
    int c = ((blockIdx.x & 7) << 8) + threadIdx.x;
    float q = __expf(-__expf(tdecay[c]));
    float d = __expf(-q);
    float dL = __expf(-q * (float)L_CHUNK);
    float eu = __expf(tfirst[c]);

    float A = 0.f, B = 0.f;
    for (int t = 0; t < s; t++) {
        A = dL * A + g_carryA[t * C_DIM + c];
        B = dL * B + g_carryB[t * C_DIM + c];
    }

    int base = s * L_CHUNK;
    for (int j = 0; j < L_CHUNK; j++) {
        size_t off = (size_t)(base + j) * C_DIM + c;
        float kk = __half2float(g_kh[off]);
        float vv = __half2float(g_vh[off]);
        float rr = __half2float(g_rh[off]);
        float e = __expf(kk);
        float eue = eu * e;
        float wkv = (A + eue * vv) / (B + eue);
        float sr = 1.f / (1.f + __expf(-rr));
        g_g[off] = __float2half_rn(sr * wkv);
        A = d * A + e * vv;
        B = d * B + e;
    }
}

// ===================== launch =====================
extern "C" void kernel_launch(void* const* d_in, const int* in_sizes, int n_in,
                              void* d_out, int out_size)
{
    const float* x  = (const float*)d_in[0];
    const float* tf = (const float*)d_in[1];
    const float* td = (const float*)d_in[2];
    const float* mk = (const float*)d_in[3];
    const float* mv = (const float*)d_in[4];
    const float* mr = (const float*)d_in[5];
    const float* Wk = (const float*)d_in[6];
    const float* Wv = (const float*)d_in[7];
    const float* Wr = (const float*)d_in[8];
    const float* Wo = (const float*)d_in[9];
    float* out = (float*)d_out;

    static cudaStream_t side = nullptr;
    static cudaEvent_t evFork, evW, evP1, ev31;
    if (!side) {
        cudaStreamCreateWithFlags(&side, cudaStreamNonBlocking);
        cudaEventCreateWithFlags(&evFork, cudaEventDisableTiming);
        cudaEventCreateWithFlags(&evW,  cudaEventDisableTiming);
        cudaEventCreateWithFlags(&evP1, cudaEventDisableTiming);
        cudaEventCreateWithFlags(&ev31, cudaEventDisableTiming);
        cudaFuncSetAttribute(gemm_qkv, cudaFuncAttributeMaxDynamicSharedMemorySize, SMEM_TOTAL);
        cudaFuncSetAttribute(gemm_out, cudaFuncAttributeMaxDynamicSharedMemorySize, SMEM_TOTAL);
    }

    // fork side stream INTO the capture graph (must originate from base stream)
    cudaEventRecord(evFork, 0);
    cudaStreamWaitEvent(side, evFork, 0);

    // weight transposes on side, concurrent with mix on base
    dim3 wgrid(C_DIM / 32, K_DIM / 32, 4), wblk(32, 8);
    wsplit_quad<<<wgrid, wblk, 0, side>>>(Wk, Wv, Wr, Wo);
    cudaEventRecord(evW, side);

    mix_split<<<(T_DIM * C_DIM / 4) / 256, 256>>>(x, mk, mv, mr);
    cudaStreamWaitEvent(0, evW, 0);

    // fused k/v/r projections (single launch, 1536 CTAs)
    dim3 gqkv(C_DIM / 128, T_DIM / 128, 3);
    gemm_qkv<<<gqkv, 512, SMEM_TOTAL>>>();

    // WKV pass1 (carries)
    wkv_pass1<<<S_CHUNKS * 8, 256>>>(td);
    cudaEventRecord(evP1, 0);

    // pass3 halves: h0 on base, h1 on side (concurrent)
    cudaStreamWaitEvent(side, evP1, 0);
    wkv_pass3<<<(S_CHUNKS / 2) * 8, 256, 0, side>>>(td, tf, S_CHUNKS / 2);
    cudaEventRecord(ev31, side);
    wkv_pass3<<<(S_CHUNKS / 2) * 8, 256>>>(td, tf, 0);

    // output projection: h0 after pass3-h0; h1 after side-stream pass3-h1
    dim3 go(C_DIM / 128, T_DIM / 256);    // 256 CTAs per half
    gemm_out<<<go, 512, SMEM_TOTAL>>>(out, 0);
    cudaStreamWaitEvent(0, ev31, 0);
    gemm_out<<<go, 512, SMEM_TOTAL>>>(out, T_DIM / 2);
}